// round 1
// baseline (speedup 1.0000x reference)
#include <cuda_runtime.h>
#include <math.h>

#define NT 8192   // B*C tokens
#define HD 1024
#define TT 3
#define EE 6

// ---- scratch (device globals; no allocation allowed) ----
__device__ float g_x1[NT * HD];          // relu(encs@fc1+b1)
__device__ float g_x[NT * HD];           // shared-bottom output
__device__ float g_gates[NT * TT * EE];  // [n][t][e]
__device__ float g_s[NT * EE * TT];      // [n][e][t]  s = h . w2t (atomically accumulated)
__device__ float g_w2t[EE * HD * TT];    // [e][f][t]  w2 @ tower_w^T
__device__ float g_b2dot[EE * TT];       // [e][t]
__device__ float g_imp[TT * EE];
__device__ float g_load[TT * EE];
__device__ float g_bce[1];

constexpr int BM = 128, BN = 128, BK = 8, TM = 8, TN = 8;

// MODE 0: fc2 (A=g_x1, bias, no relu) -> g_x
// MODE 1: fc1 (A=encs param, bias+relu) -> g_x1
// MODE 2: expert w1 (A=g_x, bias+relu) -> fused s-epilogue into g_s (no C write)
template <int MODE>
__global__ __launch_bounds__(256) void sgemm_k(const float* __restrict__ A_in,
                                               const float* __restrict__ Bw,
                                               const float* __restrict__ bias) {
    const int K = HD, Nn = HD;
    const int e = blockIdx.z;
    const float* A = (MODE == 1) ? A_in : (MODE == 0 ? g_x1 : g_x);
    const float* Bp = Bw + (size_t)e * K * Nn;
    const float* bp = bias + (size_t)e * Nn;

    __shared__ float As[BK][BM];
    __shared__ float Bs[BK][BN + 4];

    const int tid = threadIdx.x;
    const int tr = tid >> 4, tc = tid & 15;
    const int rb = blockIdx.y * BM, cb = blockIdx.x * BN;
    const int aRow = tid >> 1, aCol = (tid & 1) << 2;
    const int bRow = tid >> 5, bCol = (tid & 31) << 2;

    const float* Ap = A + (size_t)(rb + aRow) * K + aCol;
    const float* Bpp = Bp + (size_t)bRow * Nn + cb + bCol;

    float acc[TM][TN];
#pragma unroll
    for (int i = 0; i < TM; i++)
#pragma unroll
        for (int j = 0; j < TN; j++) acc[i][j] = 0.f;

    for (int k0 = 0; k0 < K; k0 += BK) {
        float4 av = *(const float4*)(Ap + k0);
        As[aCol + 0][aRow] = av.x;
        As[aCol + 1][aRow] = av.y;
        As[aCol + 2][aRow] = av.z;
        As[aCol + 3][aRow] = av.w;
        *(float4*)&Bs[bRow][bCol] = *(const float4*)(Bpp + (size_t)k0 * Nn);
        __syncthreads();
#pragma unroll
        for (int k = 0; k < BK; k++) {
            float ra[TM], rbv[TN];
            *(float4*)(ra) = *(const float4*)&As[k][tr * TM];
            *(float4*)(ra + 4) = *(const float4*)&As[k][tr * TM + 4];
            *(float4*)(rbv) = *(const float4*)&Bs[k][tc * TN];
            *(float4*)(rbv + 4) = *(const float4*)&Bs[k][tc * TN + 4];
#pragma unroll
            for (int i = 0; i < TM; i++)
#pragma unroll
                for (int j = 0; j < TN; j++) acc[i][j] += ra[i] * rbv[j];
        }
        __syncthreads();
    }

    float bcol[TN];
#pragma unroll
    for (int j = 0; j < TN; j++) bcol[j] = bp[cb + tc * TN + j];

    if (MODE == 0 || MODE == 1) {
        float* Cout = (MODE == 1) ? g_x1 : g_x;
#pragma unroll
        for (int i = 0; i < TM; i++) {
            int row = rb + tr * TM + i;
            float* cr = Cout + (size_t)row * Nn + cb + tc * TN;
#pragma unroll
            for (int j = 0; j < TN; j++) {
                float v = acc[i][j] + bcol[j];
                if (MODE == 1) v = fmaxf(v, 0.f);
                cr[j] = v;
            }
        }
    } else {
        // expert epilogue: h = relu(acc+bias); s[n][e][t] += sum_f h*w2t[e][f][t]
        __shared__ float w2s[BN * TT];
        __shared__ float sred[BM * TT];
        for (int idx = tid; idx < BN * TT; idx += 256)
            w2s[idx] = g_w2t[(size_t)e * HD * TT + (size_t)cb * TT + idx];
        for (int idx = tid; idx < BM * TT; idx += 256) sred[idx] = 0.f;
        __syncthreads();
#pragma unroll
        for (int i = 0; i < TM; i++) {
            float p0 = 0.f, p1 = 0.f, p2 = 0.f;
#pragma unroll
            for (int j = 0; j < TN; j++) {
                float hv = fmaxf(acc[i][j] + bcol[j], 0.f);
                int f = tc * TN + j;
                p0 += hv * w2s[f * 3 + 0];
                p1 += hv * w2s[f * 3 + 1];
                p2 += hv * w2s[f * 3 + 2];
            }
            int r = tr * TM + i;
            atomicAdd(&sred[r * 3 + 0], p0);
            atomicAdd(&sred[r * 3 + 1], p1);
            atomicAdd(&sred[r * 3 + 2], p2);
        }
        __syncthreads();
        for (int idx = tid; idx < BM * TT; idx += 256) {
            int r = idx / 3, t = idx - 3 * r;
            atomicAdd(&g_s[((size_t)(rb + r)) * EE * TT + e * TT + t], sred[idx]);
        }
    }
}

__global__ void zero_kernel() {
    int idx = blockIdx.x * 256 + threadIdx.x;
    if (idx < NT * EE * TT) g_s[idx] = 0.f;
    if (idx < TT * EE) {
        g_imp[idx] = 0.f;
        g_load[idx] = 0.f;
    }
    if (idx == 0) g_bce[0] = 0.f;
}

// w2t[e,f,t] = sum_o w2[e,f,o] * tower_w[t,o]   (one warp per (e,f) row)
__global__ __launch_bounds__(256) void w2t_kernel(const float* __restrict__ w2,
                                                  const float* __restrict__ tw) {
    int g = blockIdx.x * 256 + threadIdx.x;
    int gw = g >> 5, lane = g & 31;
    if (gw >= EE * HD) return;
    const float* row = w2 + (size_t)gw * HD;
#pragma unroll
    for (int t = 0; t < TT; t++) {
        float a = 0.f;
        for (int o = lane; o < HD; o += 32) a += row[o] * tw[t * HD + o];
#pragma unroll
        for (int off = 16; off; off >>= 1) a += __shfl_down_sync(0xffffffffu, a, off);
        if (lane == 0) g_w2t[(size_t)gw * TT + t] = a;
    }
}

__global__ void b2dot_kernel(const float* __restrict__ b2, const float* __restrict__ tw) {
    int i = threadIdx.x;
    if (i < EE * TT) {
        int e = i / TT, t = i - TT * e;
        float a = 0.f;
        for (int o = 0; o < HD; o++) a += b2[e * HD + o] * tw[t * HD + o];
        g_b2dot[i] = a;
    }
}

// per-token gating: logits[t,e] = x[n,:] . w_gate[t,:,e]; top-3 of 6, softmax, scatter
__global__ __launch_bounds__(256) void gates_kernel(const float* __restrict__ wg) {
    int warp = threadIdx.x >> 5, lane = threadIdx.x & 31;
    int n = blockIdx.x * 8 + warp;
    const float* xr = g_x + (size_t)n * HD;
    float xv[32];
#pragma unroll
    for (int i = 0; i < 32; i++) xv[i] = xr[i * 32 + lane];
    float lg[18];
    for (int te = 0; te < 18; te++) {
        int t = te / 6, e = te - 6 * t;
        float acc = 0.f;
#pragma unroll
        for (int i = 0; i < 32; i++)
            acc += xv[i] * wg[((size_t)t * HD + i * 32 + lane) * EE + e];
#pragma unroll
        for (int off = 16; off; off >>= 1) acc += __shfl_down_sync(0xffffffffu, acc, off);
        lg[te] = acc;  // valid on lane 0
    }
    if (lane == 0) {
        for (int t = 0; t < TT; t++) {
            float v[6];
#pragma unroll
            for (int e = 0; e < 6; e++) v[e] = lg[t * 6 + e];
            bool sel[6] = {false, false, false, false, false, false};
            float m = -1e30f;
            for (int r = 0; r < 3; r++) {  // strict > : first index wins on ties (jax top_k)
                int bi = 0;
                float bv = -1e30f;
                for (int e = 0; e < 6; e++)
                    if (!sel[e] && v[e] > bv) { bv = v[e]; bi = e; }
                sel[bi] = true;
                if (r == 0) m = bv;
            }
            float sum = 0.f, gv[6];
            for (int e = 0; e < 6; e++) {
                gv[e] = sel[e] ? expf(v[e] - m) : 0.f;
                sum += gv[e];
            }
            float inv = 1.f / sum;
            for (int e = 0; e < 6; e++) {
                float gg = gv[e] * inv;
                g_gates[(size_t)n * 18 + t * 6 + e] = gg;
                if (sel[e]) {
                    atomicAdd(&g_imp[t * 6 + e], gg);
                    atomicAdd(&g_load[t * 6 + e], 1.f);
                }
            }
        }
    }
}

// towers + labels + BCE + preds. block = one b (128 blocks), thread = c (64)
__global__ void final_kernel(const float* __restrict__ scores,
                             const float* __restrict__ tower_b, float* __restrict__ out) {
    int b = blockIdx.x, c = threadIdx.x;
    int n = b * 64 + c;
    float sc[3];
#pragma unroll
    for (int t = 0; t < 3; t++) sc[t] = scores[(size_t)n * 3 + t];
    __shared__ float red[64];
    float mx[3];
    for (int t = 0; t < 3; t++) {
        red[c] = sc[t];
        __syncthreads();
        for (int off = 32; off; off >>= 1) {
            if (c < off) red[c] = fmaxf(red[c], red[c + off]);
            __syncthreads();
        }
        mx[t] = red[0];
        __syncthreads();
    }
    float zsum = 0.f, bsum = 0.f;
#pragma unroll
    for (int t = 0; t < 3; t++) {
        float z = tower_b[t];
#pragma unroll
        for (int e = 0; e < 6; e++)
            z += g_gates[(size_t)n * 18 + t * 6 + e] *
                 (g_s[(size_t)n * 18 + e * 3 + t] + g_b2dot[e * 3 + t]);
        float label = (sc[t] == mx[t]) ? 1.f : 0.f;
        bsum += fmaxf(z, 0.f) - z * label + log1pf(expf(-fabsf(z)));
        zsum += z;
    }
    out[1 + n] = 1.f / (1.f + expf(-zsum / 3.f));
    red[c] = bsum;
    __syncthreads();
    for (int off = 32; off; off >>= 1) {
        if (c < off) red[c] += red[c + off];
        __syncthreads();
    }
    if (c == 0) atomicAdd(&g_bce[0], red[0]);
}

__global__ void finalize_kernel(float* __restrict__ out) {
    if (threadIdx.x == 0 && blockIdx.x == 0) {
        float aux = 0.f;
        for (int t = 0; t < 3; t++) {
            for (int which = 0; which < 2; which++) {
                const float* v = which ? &g_load[t * 6] : &g_imp[t * 6];
                float m = 0.f;
                for (int e = 0; e < 6; e++) m += v[e];
                m *= (1.f / 6.f);
                float var = 0.f;
                for (int e = 0; e < 6; e++) {
                    float d = v[e] - m;
                    var += d * d;
                }
                var *= (1.f / 5.f);  // ddof=1
                aux += var / (m * m + 1e-10f);
            }
        }
        out[0] = g_bce[0] / 24576.f + 0.01f * aux;
    }
}

extern "C" void kernel_launch(void* const* d_in, const int* in_sizes, int n_in,
                              void* d_out, int out_size) {
    const float* encs   = (const float*)d_in[0];
    const float* scores = (const float*)d_in[1];
    const float* fc1_w  = (const float*)d_in[2];
    const float* fc1_b  = (const float*)d_in[3];
    const float* fc2_w  = (const float*)d_in[4];
    const float* fc2_b  = (const float*)d_in[5];
    const float* w_gate = (const float*)d_in[6];
    const float* ew1    = (const float*)d_in[7];
    const float* eb1    = (const float*)d_in[8];
    const float* ew2    = (const float*)d_in[9];
    const float* eb2    = (const float*)d_in[10];
    const float* tw     = (const float*)d_in[11];
    const float* tb     = (const float*)d_in[12];
    float* out = (float*)d_out;

    zero_kernel<<<(NT * EE * TT + 255) / 256, 256>>>();
    w2t_kernel<<<(EE * HD * 32 + 255) / 256, 256>>>(ew2, tw);
    b2dot_kernel<<<1, 32>>>(eb2, tw);

    dim3 g1(HD / BN, NT / BM, 1);
    sgemm_k<1><<<g1, 256>>>(encs, fc1_w, fc1_b);   // x1 = relu(encs@fc1+b)
    sgemm_k<0><<<g1, 256>>>(nullptr, fc2_w, fc2_b); // x = x1@fc2+b

    gates_kernel<<<NT / 8, 256>>>(w_gate);

    dim3 ge(HD / BN, NT / BM, EE);
    sgemm_k<2><<<ge, 256>>>(nullptr, ew1, eb1);     // fused expert up-proj + s

    final_kernel<<<128, 64>>>(scores, tb, out);
    finalize_kernel<<<1, 32>>>(out);
}

// round 5
// speedup vs baseline: 3.1752x; 3.1752x over previous
#include <cuda_runtime.h>
#include <math.h>
#include <cstdint>

#define NT 8192   // B*C tokens
#define HD 1024
#define TT 3
#define EE 6

// ---- scratch (device globals; no allocation allowed) ----
__device__ float g_enc[NT * HD];        // tf32-rounded encs
__device__ float g_x1[NT * HD];
__device__ float g_x[NT * HD];
__device__ float g_wt1[HD * HD];        // fc1_w^T (tf32-rounded)
__device__ float g_wt2[HD * HD];        // fc2_w^T
__device__ float g_wte[EE * HD * HD];   // expert_w1^T per expert
__device__ float g_gates[NT * TT * EE];
__device__ float g_s[NT * EE * TT];
__device__ float g_w2t[EE * HD * TT];
__device__ float g_b2dot[EE * TT];
__device__ float g_imp[TT * EE];
__device__ float g_load[TT * EE];
__device__ float g_bce[1];

// ======================= helpers =======================
__device__ __forceinline__ uint32_t smem_u32(const void* p) {
    uint32_t a;
    asm("{ .reg .u64 t; cvta.to.shared.u64 t, %1; cvt.u32.u64 %0, t; }" : "=r"(a) : "l"(p));
    return a;
}
// tf32 destination is a .b32 register in PTX; result is an fp32 bit-pattern
// with low mantissa bits cleared (round-to-nearest-even on bit 13: rna).
__device__ __forceinline__ float to_tf32(float x) {
    uint32_t r;
    asm("cvt.rna.tf32.f32 %0, %1;" : "=r"(r) : "f"(x));
    return __uint_as_float(r);
}
__device__ __forceinline__ void cpa16(uint32_t dst, const void* src) {
    asm volatile("cp.async.cg.shared.global [%0], [%1], 16;" :: "r"(dst), "l"(src));
}
#define CPA_COMMIT() asm volatile("cp.async.commit_group;" ::: "memory")
#define CPA_WAIT(n)  asm volatile("cp.async.wait_group %0;" :: "n"(n) : "memory")

__device__ __forceinline__ void mma8(float* c, const uint32_t* a, const uint32_t* b) {
    asm volatile(
        "mma.sync.aligned.m16n8k8.row.col.f32.tf32.tf32.f32 "
        "{%0,%1,%2,%3}, {%4,%5,%6,%7}, {%8,%9}, {%0,%1,%2,%3};"
        : "+f"(c[0]), "+f"(c[1]), "+f"(c[2]), "+f"(c[3])
        : "r"(a[0]), "r"(a[1]), "r"(a[2]), "r"(a[3]), "r"(b[0]), "r"(b[1]));
}

// ======================= tf32 mma.sync GEMM =======================
// C[8192,1024] = A[8192,1024] @ W[1024,1024]; B operand = W^T (row n, k contiguous).
constexpr int BM = 128, BN = 128, BK = 16, BKP = 20;
constexpr int NS = HD / BK;              // 64 slabs
constexpr int STG = (BM + BN) * BKP;     // floats per stage = 5120
constexpr int GSMEM = 3 * STG * 4;       // 61440 B

// MODE 0: fc2 (A=g_x1 -> g_x, bias)  MODE 1: fc1 (A=g_enc -> g_x1, bias+relu)
// MODE 2: expert (A=g_x, bias+relu, fused s-epilogue)
template <int MODE>
__global__ __launch_bounds__(256, 2) void gemm_mma(const float* __restrict__ bias_in) {
    extern __shared__ float sm[];
    const uint32_t sb = smem_u32(sm);
    const int tid = threadIdx.x;
    const int wid = tid >> 5, lane = tid & 31;
    const int wm = wid >> 2, wn = wid & 3;     // warp grid 2(M) x 4(N)
    const int gr = lane >> 2, tq = lane & 3;   // quad row / quad col
    const int e = blockIdx.z;
    const int rb = blockIdx.y * BM, cb = blockIdx.x * BN;

    const float* A = (MODE == 1) ? g_enc : (MODE == 0 ? g_x1 : g_x);
    const float* Bw = (MODE == 1) ? g_wt1 : (MODE == 0 ? g_wt2 : g_wte + (size_t)e * HD * HD);
    const float* bp = bias_in + (MODE == 2 ? (size_t)e * HD : 0);

    float C[4][4][4];
#pragma unroll
    for (int i = 0; i < 4; i++)
#pragma unroll
        for (int j = 0; j < 4; j++)
#pragma unroll
            for (int q = 0; q < 4; q++) C[i][j][q] = 0.f;

    // ---- slab loader: slab p -> stage s ----
    auto load_slab = [&](int p, int s) {
        const int k0 = p * BK;
        const uint32_t As_a = sb + (uint32_t)(s * STG) * 4;
        const uint32_t Bs_a = As_a + (uint32_t)(BM * BKP) * 4;
#pragma unroll
        for (int j = 0; j < 2; j++) {
            int c = tid + j * 256;               // 0..511
            int row = c >> 2, seg = c & 3;       // 128 rows x 4 16B-segs
            uint32_t off = (uint32_t)(row * BKP + seg * 4) * 4;
            cpa16(As_a + off, A + (size_t)(rb + row) * HD + k0 + seg * 4);
            cpa16(Bs_a + off, Bw + (size_t)(cb + row) * HD + k0 + seg * 4);
        }
        CPA_COMMIT();
    };

    load_slab(0, 0);
    load_slab(1, 1);

    for (int i = 0; i < NS; i++) {
        if (i + 1 < NS) { CPA_WAIT(1); } else { CPA_WAIT(0); }
        __syncthreads();
        if (i + 2 < NS) load_slab(i + 2, (i + 2) % 3);

        const float* As = sm + (i % 3) * STG;
        const float* Bs = As + BM * BKP;
#pragma unroll
        for (int ks = 0; ks < 2; ks++) {
            const int k0 = ks * 8;
            uint32_t a[4][4], b[4][2];
#pragma unroll
            for (int mt = 0; mt < 4; mt++) {
                int r0 = wm * 64 + mt * 16 + gr;
                a[mt][0] = __float_as_uint(As[r0 * BKP + k0 + tq]);
                a[mt][1] = __float_as_uint(As[(r0 + 8) * BKP + k0 + tq]);
                a[mt][2] = __float_as_uint(As[r0 * BKP + k0 + 4 + tq]);
                a[mt][3] = __float_as_uint(As[(r0 + 8) * BKP + k0 + 4 + tq]);
            }
#pragma unroll
            for (int nt = 0; nt < 4; nt++) {
                int n0 = wn * 32 + nt * 8 + gr;
                b[nt][0] = __float_as_uint(Bs[n0 * BKP + k0 + tq]);
                b[nt][1] = __float_as_uint(Bs[n0 * BKP + k0 + 4 + tq]);
            }
#pragma unroll
            for (int mt = 0; mt < 4; mt++)
#pragma unroll
                for (int nt = 0; nt < 4; nt++) mma8(C[mt][nt], a[mt], b[nt]);
        }
        __syncthreads();
    }

    // ---- epilogue (smem stages are free; re-sync'd above) ----
    if (MODE == 2) {
        float* w2t_s = sm;            // 384
        float* bias_s = sm + 384;     // 128
        float* sred = sm + 512;       // 128*12 = 1536
        if (tid < 128) bias_s[tid] = bp[cb + tid];
        for (int idx = tid; idx < 384; idx += 256)
            w2t_s[idx] = g_w2t[(size_t)e * HD * 3 + (size_t)cb * 3 + idx];
        __syncthreads();
#pragma unroll
        for (int mt = 0; mt < 4; mt++) {
#pragma unroll
            for (int pair = 0; pair < 2; pair++) {
                float p0 = 0.f, p1 = 0.f, p2 = 0.f;
#pragma unroll
                for (int nt = 0; nt < 4; nt++) {
                    int cl = wn * 32 + nt * 8 + tq * 2;
                    float h0 = fmaxf(C[mt][nt][pair * 2 + 0] + bias_s[cl], 0.f);
                    float h1 = fmaxf(C[mt][nt][pair * 2 + 1] + bias_s[cl + 1], 0.f);
                    p0 += h0 * w2t_s[cl * 3 + 0] + h1 * w2t_s[(cl + 1) * 3 + 0];
                    p1 += h0 * w2t_s[cl * 3 + 1] + h1 * w2t_s[(cl + 1) * 3 + 1];
                    p2 += h0 * w2t_s[cl * 3 + 2] + h1 * w2t_s[(cl + 1) * 3 + 2];
                }
                p0 += __shfl_down_sync(0xffffffffu, p0, 2);
                p0 += __shfl_down_sync(0xffffffffu, p0, 1);
                p1 += __shfl_down_sync(0xffffffffu, p1, 2);
                p1 += __shfl_down_sync(0xffffffffu, p1, 1);
                p2 += __shfl_down_sync(0xffffffffu, p2, 2);
                p2 += __shfl_down_sync(0xffffffffu, p2, 1);
                if (tq == 0) {
                    int rl = wm * 64 + mt * 16 + pair * 8 + gr;
                    sred[rl * 12 + wn * 3 + 0] = p0;
                    sred[rl * 12 + wn * 3 + 1] = p1;
                    sred[rl * 12 + wn * 3 + 2] = p2;
                }
            }
        }
        __syncthreads();
        if (tid < 128) {
#pragma unroll
            for (int t = 0; t < 3; t++) {
                float s = sred[tid * 12 + t] + sred[tid * 12 + 3 + t] +
                          sred[tid * 12 + 6 + t] + sred[tid * 12 + 9 + t];
                atomicAdd(&g_s[(size_t)(rb + tid) * 18 + e * 3 + t], s);
            }
        }
    } else {
        float* bias_s = sm;
        if (tid < 128) bias_s[tid] = bp[cb + tid];
        __syncthreads();
        float* out = (MODE == 1) ? g_x1 : g_x;
#pragma unroll
        for (int mt = 0; mt < 4; mt++) {
#pragma unroll
            for (int nt = 0; nt < 4; nt++) {
                int row = rb + wm * 64 + mt * 16 + gr;
                int cl = wn * 32 + nt * 8 + tq * 2;
                float v0 = C[mt][nt][0] + bias_s[cl];
                float v1 = C[mt][nt][1] + bias_s[cl + 1];
                float v2 = C[mt][nt][2] + bias_s[cl];
                float v3 = C[mt][nt][3] + bias_s[cl + 1];
                if (MODE == 1) {
                    v0 = fmaxf(v0, 0.f); v1 = fmaxf(v1, 0.f);
                    v2 = fmaxf(v2, 0.f); v3 = fmaxf(v3, 0.f);
                }
                float2 w0 = make_float2(to_tf32(v0), to_tf32(v1));
                float2 w1 = make_float2(to_tf32(v2), to_tf32(v3));
                *(float2*)(out + (size_t)row * HD + cb + cl) = w0;
                *(float2*)(out + (size_t)(row + 8) * HD + cb + cl) = w1;
            }
        }
    }
}

// ======================= small kernels =======================
__global__ void conv_tf32_k(const float* __restrict__ in, float* __restrict__ out) {
    int idx = blockIdx.x * 256 + threadIdx.x;
    float4 v = ((const float4*)in)[idx];
    v.x = to_tf32(v.x); v.y = to_tf32(v.y); v.z = to_tf32(v.z); v.w = to_tf32(v.w);
    ((float4*)out)[idx] = v;
}

__global__ void transpose_k(const float* __restrict__ W, float* __restrict__ WT) {
    __shared__ float t[32][33];
    const float* Ws = W + (size_t)blockIdx.z * HD * HD;
    float* Ts = WT + (size_t)blockIdx.z * HD * HD;
    int bx = blockIdx.x * 32, by = blockIdx.y * 32;
#pragma unroll
    for (int j = 0; j < 4; j++)
        t[threadIdx.y + 8 * j][threadIdx.x] =
            Ws[(size_t)(by + threadIdx.y + 8 * j) * HD + bx + threadIdx.x];
    __syncthreads();
#pragma unroll
    for (int j = 0; j < 4; j++)
        Ts[(size_t)(bx + threadIdx.y + 8 * j) * HD + by + threadIdx.x] =
            to_tf32(t[threadIdx.x][threadIdx.y + 8 * j]);
}

__global__ void zero_kernel() {
    int idx = blockIdx.x * 256 + threadIdx.x;
    if (idx < NT * EE * TT) g_s[idx] = 0.f;
    if (idx < TT * EE) { g_imp[idx] = 0.f; g_load[idx] = 0.f; }
    if (idx == 0) g_bce[0] = 0.f;
}

__global__ __launch_bounds__(256) void w2t_kernel(const float* __restrict__ w2,
                                                  const float* __restrict__ tw) {
    int g = blockIdx.x * 256 + threadIdx.x;
    int gw = g >> 5, lane = g & 31;
    if (gw >= EE * HD) return;
    const float* row = w2 + (size_t)gw * HD;
#pragma unroll
    for (int t = 0; t < TT; t++) {
        float a = 0.f;
        for (int o = lane; o < HD; o += 32) a += row[o] * tw[t * HD + o];
#pragma unroll
        for (int off = 16; off; off >>= 1) a += __shfl_down_sync(0xffffffffu, a, off);
        if (lane == 0) g_w2t[(size_t)gw * TT + t] = a;
    }
}

__global__ void b2dot_kernel(const float* __restrict__ b2, const float* __restrict__ tw) {
    int i = threadIdx.x;
    if (i < EE * TT) {
        int e = i / TT, t = i - TT * e;
        float a = 0.f;
        for (int o = 0; o < HD; o++) a += b2[e * HD + o] * tw[t * HD + o];
        g_b2dot[i] = a;
    }
}

__global__ __launch_bounds__(256) void gates_kernel(const float* __restrict__ wg) {
    int warp = threadIdx.x >> 5, lane = threadIdx.x & 31;
    int n = blockIdx.x * 8 + warp;
    const float* xr = g_x + (size_t)n * HD;
    float xv[32];
#pragma unroll
    for (int i = 0; i < 32; i++) xv[i] = xr[i * 32 + lane];
    float lg[18];
    for (int te = 0; te < 18; te++) {
        int t = te / 6, e = te - 6 * t;
        float acc = 0.f;
#pragma unroll
        for (int i = 0; i < 32; i++)
            acc += xv[i] * wg[((size_t)t * HD + i * 32 + lane) * EE + e];
#pragma unroll
        for (int off = 16; off; off >>= 1) acc += __shfl_down_sync(0xffffffffu, acc, off);
        lg[te] = acc;
    }
    if (lane == 0) {
        for (int t = 0; t < TT; t++) {
            float v[6];
#pragma unroll
            for (int e = 0; e < 6; e++) v[e] = lg[t * 6 + e];
            bool sel[6] = {false, false, false, false, false, false};
            float m = -1e30f;
            for (int r = 0; r < 3; r++) {  // strict >: first index wins (jax top_k)
                int bi = 0; float bv = -1e30f;
                for (int e = 0; e < 6; e++)
                    if (!sel[e] && v[e] > bv) { bv = v[e]; bi = e; }
                sel[bi] = true;
                if (r == 0) m = bv;
            }
            float sum = 0.f, gv[6];
            for (int e = 0; e < 6; e++) { gv[e] = sel[e] ? expf(v[e] - m) : 0.f; sum += gv[e]; }
            float inv = 1.f / sum;
            for (int e = 0; e < 6; e++) {
                float gg = gv[e] * inv;
                g_gates[(size_t)n * 18 + t * 6 + e] = gg;
                if (sel[e]) {
                    atomicAdd(&g_imp[t * 6 + e], gg);
                    atomicAdd(&g_load[t * 6 + e], 1.f);
                }
            }
        }
    }
}

__global__ void final_kernel(const float* __restrict__ scores,
                             const float* __restrict__ tower_b, float* __restrict__ out) {
    int b = blockIdx.x, c = threadIdx.x;
    int n = b * 64 + c;
    float sc[3];
#pragma unroll
    for (int t = 0; t < 3; t++) sc[t] = scores[(size_t)n * 3 + t];
    __shared__ float red[64];
    float mx[3];
    for (int t = 0; t < 3; t++) {
        red[c] = sc[t];
        __syncthreads();
        for (int off = 32; off; off >>= 1) {
            if (c < off) red[c] = fmaxf(red[c], red[c + off]);
            __syncthreads();
        }
        mx[t] = red[0];
        __syncthreads();
    }
    float zsum = 0.f, bsum = 0.f;
#pragma unroll
    for (int t = 0; t < 3; t++) {
        float z = tower_b[t];
#pragma unroll
        for (int e = 0; e < 6; e++)
            z += g_gates[(size_t)n * 18 + t * 6 + e] *
                 (g_s[(size_t)n * 18 + e * 3 + t] + g_b2dot[e * 3 + t]);
        float label = (sc[t] == mx[t]) ? 1.f : 0.f;
        bsum += fmaxf(z, 0.f) - z * label + log1pf(expf(-fabsf(z)));
        zsum += z;
    }
    out[1 + n] = 1.f / (1.f + expf(-zsum / 3.f));
    red[c] = bsum;
    __syncthreads();
    for (int off = 32; off; off >>= 1) {
        if (c < off) red[c] += red[c + off];
        __syncthreads();
    }
    if (c == 0) atomicAdd(&g_bce[0], red[0]);
}

__global__ void finalize_kernel(float* __restrict__ out) {
    if (threadIdx.x == 0 && blockIdx.x == 0) {
        float aux = 0.f;
        for (int t = 0; t < 3; t++) {
            for (int which = 0; which < 2; which++) {
                const float* v = which ? &g_load[t * 6] : &g_imp[t * 6];
                float m = 0.f;
                for (int e = 0; e < 6; e++) m += v[e];
                m *= (1.f / 6.f);
                float var = 0.f;
                for (int e = 0; e < 6; e++) { float d = v[e] - m; var += d * d; }
                var *= (1.f / 5.f);  // ddof=1
                aux += var / (m * m + 1e-10f);
            }
        }
        out[0] = g_bce[0] / 24576.f + 0.01f * aux;
    }
}

// ======================= launch =======================
extern "C" void kernel_launch(void* const* d_in, const int* in_sizes, int n_in,
                              void* d_out, int out_size) {
    const float* encs   = (const float*)d_in[0];
    const float* scores = (const float*)d_in[1];
    const float* fc1_w  = (const float*)d_in[2];
    const float* fc1_b  = (const float*)d_in[3];
    const float* fc2_w  = (const float*)d_in[4];
    const float* fc2_b  = (const float*)d_in[5];
    const float* w_gate = (const float*)d_in[6];
    const float* ew1    = (const float*)d_in[7];
    const float* eb1    = (const float*)d_in[8];
    const float* ew2    = (const float*)d_in[9];
    const float* eb2    = (const float*)d_in[10];
    const float* tw     = (const float*)d_in[11];
    const float* tb     = (const float*)d_in[12];
    float* out = (float*)d_out;

    cudaFuncSetAttribute(gemm_mma<0>, cudaFuncAttributeMaxDynamicSharedMemorySize, GSMEM);
    cudaFuncSetAttribute(gemm_mma<1>, cudaFuncAttributeMaxDynamicSharedMemorySize, GSMEM);
    cudaFuncSetAttribute(gemm_mma<2>, cudaFuncAttributeMaxDynamicSharedMemorySize, GSMEM);

    float *enc_p, *wt1, *wt2, *wte;
    cudaGetSymbolAddress((void**)&enc_p, g_enc);
    cudaGetSymbolAddress((void**)&wt1, g_wt1);
    cudaGetSymbolAddress((void**)&wt2, g_wt2);
    cudaGetSymbolAddress((void**)&wte, g_wte);

    zero_kernel<<<(NT * EE * TT + 255) / 256, 256>>>();
    conv_tf32_k<<<NT * HD / 4 / 256, 256>>>(encs, enc_p);
    transpose_k<<<dim3(32, 32, 1), dim3(32, 8)>>>(fc1_w, wt1);
    transpose_k<<<dim3(32, 32, 1), dim3(32, 8)>>>(fc2_w, wt2);
    transpose_k<<<dim3(32, 32, EE), dim3(32, 8)>>>(ew1, wte);
    w2t_kernel<<<(EE * HD * 32 + 255) / 256, 256>>>(ew2, tw);
    b2dot_kernel<<<1, 32>>>(eb2, tw);

    dim3 gfc(HD / BN, NT / BM, 1);
    gemm_mma<1><<<gfc, 256, GSMEM>>>(fc1_b);   // x1 = relu(encs@fc1+b)
    gemm_mma<0><<<gfc, 256, GSMEM>>>(fc2_b);   // x = x1@fc2+b

    gates_kernel<<<NT / 8, 256>>>(w_gate);

    dim3 ge(HD / BN, NT / BM, EE);
    gemm_mma<2><<<ge, 256, GSMEM>>>(eb1);      // fused expert up-proj + s

    final_kernel<<<128, 64>>>(scores, tb, out);
    finalize_kernel<<<1, 32>>>(out);
}

// round 6
// speedup vs baseline: 5.1602x; 1.6251x over previous
#include <cuda_runtime.h>
#include <cuda_fp16.h>
#include <math.h>
#include <cstdint>

#define NT 8192   // B*C tokens
#define HD 1024
#define TT 3
#define EE 6

// ---- scratch (device globals; no allocation allowed) ----
__device__ __half g_ench[NT * HD];       // fp16 encs
__device__ __half g_x1h[NT * HD];        // fp16 relu(fc1)
__device__ float  g_x[NT * HD];          // fp32 shared-bottom out (for gates)
__device__ __half g_xh[NT * HD];         // fp16 copy (expert GEMM A)
__device__ __half g_wt1h[HD * HD];       // fc1_w^T fp16
__device__ __half g_wt2h[HD * HD];       // fc2_w^T fp16
__device__ __half g_wteh[EE * HD * HD];  // expert_w1^T fp16
__device__ float g_gates[NT * TT * EE];
__device__ float g_s[NT * EE * TT];
__device__ float g_w2t[EE * HD * TT];
__device__ float g_b2dot[EE * TT];
__device__ float g_imp[TT * EE];
__device__ float g_load[TT * EE];
__device__ float g_bce[1];

// ======================= helpers =======================
__device__ __forceinline__ uint32_t smem_u32(const void* p) {
    uint32_t a;
    asm("{ .reg .u64 t; cvta.to.shared.u64 t, %1; cvt.u32.u64 %0, t; }" : "=r"(a) : "l"(p));
    return a;
}
__device__ __forceinline__ void cpa16(uint32_t dst, const void* src) {
    asm volatile("cp.async.cg.shared.global [%0], [%1], 16;" :: "r"(dst), "l"(src));
}
#define CPA_COMMIT() asm volatile("cp.async.commit_group;" ::: "memory")
#define CPA_WAIT(n)  asm volatile("cp.async.wait_group %0;" :: "n"(n) : "memory")

__device__ __forceinline__ void mma16(float* c, const uint32_t* a, const uint32_t* b) {
    asm volatile(
        "mma.sync.aligned.m16n8k16.row.col.f32.f16.f16.f32 "
        "{%0,%1,%2,%3}, {%4,%5,%6,%7}, {%8,%9}, {%0,%1,%2,%3};"
        : "+f"(c[0]), "+f"(c[1]), "+f"(c[2]), "+f"(c[3])
        : "r"(a[0]), "r"(a[1]), "r"(a[2]), "r"(a[3]), "r"(b[0]), "r"(b[1]));
}

// ======================= fp16 mma.sync GEMM =======================
// C[8192,1024] = A[8192,1024] @ W[1024,1024]; B operand = W^T (row n, k contiguous).
constexpr int BM = 128, BN = 128;
constexpr int BKH = 32;                  // k-halves per slab
constexpr int BKP = 40;                  // padded row length in halves (80 B)
constexpr int NS = HD / BKH;             // 32 slabs
constexpr int STG_B = (BM + BN) * BKP * 2;  // 20480 bytes per stage
constexpr int GSMEM = 3 * STG_B;            // 61440 B

// MODE 0: fc2 (A=g_x1h -> g_x fp32 + g_xh fp16)  MODE 1: fc1 (A=g_ench -> g_x1h, relu)
// MODE 2: expert (A=g_xh, bias+relu, fused s-epilogue)
template <int MODE>
__global__ __launch_bounds__(256, 2) void gemm_mma(const float* __restrict__ bias_in) {
    extern __shared__ __align__(16) char smb[];
    const uint32_t sb = smem_u32(smb);
    float* smf = (float*)smb;
    const int tid = threadIdx.x;
    const int wid = tid >> 5, lane = tid & 31;
    const int wm = wid >> 2, wn = wid & 3;     // warp grid 2(M) x 4(N)
    const int gr = lane >> 2, tq = lane & 3;   // quad row / quad col
    const int e = blockIdx.z;
    const int rb = blockIdx.y * BM, cb = blockIdx.x * BN;

    const __half* A = (MODE == 1) ? g_ench : (MODE == 0 ? g_x1h : g_xh);
    const __half* Bw = (MODE == 1) ? g_wt1h
                                   : (MODE == 0 ? g_wt2h : g_wteh + (size_t)e * HD * HD);
    const float* bp = bias_in + (MODE == 2 ? (size_t)e * HD : 0);

    float C[4][4][4];
#pragma unroll
    for (int i = 0; i < 4; i++)
#pragma unroll
        for (int j = 0; j < 4; j++)
#pragma unroll
            for (int q = 0; q < 4; q++) C[i][j][q] = 0.f;

    // ---- slab loader: slab p -> stage s (rows of 32 halves = 4x16B segs) ----
    auto load_slab = [&](int p, int s) {
        const int k0 = p * BKH;
        const uint32_t As_a = sb + (uint32_t)(s * STG_B);
        const uint32_t Bs_a = As_a + (uint32_t)(BM * BKP * 2);
#pragma unroll
        for (int j = 0; j < 2; j++) {
            int c = tid + j * 256;               // 0..511
            int row = c >> 2, seg = c & 3;
            uint32_t off = (uint32_t)(row * BKP * 2 + seg * 16);
            cpa16(As_a + off, A + (size_t)(rb + row) * HD + k0 + seg * 8);
            cpa16(Bs_a + off, Bw + (size_t)(cb + row) * HD + k0 + seg * 8);
        }
        CPA_COMMIT();
    };

    load_slab(0, 0);
    load_slab(1, 1);

    for (int i = 0; i < NS; i++) {
        if (i + 1 < NS) { CPA_WAIT(1); } else { CPA_WAIT(0); }
        __syncthreads();
        if (i + 2 < NS) load_slab(i + 2, (i + 2) % 3);

        const __half* Ash = (const __half*)(smb + (i % 3) * STG_B);
        const __half* Bsh = Ash + BM * BKP;
#pragma unroll
        for (int ks = 0; ks < 2; ks++) {
            const int k0 = ks * 16;  // halves
            uint32_t a[4][4], b[4][2];
#pragma unroll
            for (int mt = 0; mt < 4; mt++) {
                int r0 = wm * 64 + mt * 16 + gr;
                a[mt][0] = *(const uint32_t*)(Ash + r0 * BKP + k0 + 2 * tq);
                a[mt][1] = *(const uint32_t*)(Ash + (r0 + 8) * BKP + k0 + 2 * tq);
                a[mt][2] = *(const uint32_t*)(Ash + r0 * BKP + k0 + 8 + 2 * tq);
                a[mt][3] = *(const uint32_t*)(Ash + (r0 + 8) * BKP + k0 + 8 + 2 * tq);
            }
#pragma unroll
            for (int nt = 0; nt < 4; nt++) {
                int n0 = wn * 32 + nt * 8 + gr;
                b[nt][0] = *(const uint32_t*)(Bsh + n0 * BKP + k0 + 2 * tq);
                b[nt][1] = *(const uint32_t*)(Bsh + n0 * BKP + k0 + 8 + 2 * tq);
            }
#pragma unroll
            for (int mt = 0; mt < 4; mt++)
#pragma unroll
                for (int nt = 0; nt < 4; nt++) mma16(C[mt][nt], a[mt], b[nt]);
        }
        __syncthreads();
    }

    // ---- epilogue ----
    if (MODE == 2) {
        float* w2t_s = smf;            // 384
        float* bias_s = smf + 384;     // 128
        float* sred = smf + 512;       // 128*12
        if (tid < 128) bias_s[tid] = bp[cb + tid];
        for (int idx = tid; idx < 384; idx += 256)
            w2t_s[idx] = g_w2t[(size_t)e * HD * 3 + (size_t)cb * 3 + idx];
        __syncthreads();
#pragma unroll
        for (int mt = 0; mt < 4; mt++) {
#pragma unroll
            for (int pair = 0; pair < 2; pair++) {
                float p0 = 0.f, p1 = 0.f, p2 = 0.f;
#pragma unroll
                for (int nt = 0; nt < 4; nt++) {
                    int cl = wn * 32 + nt * 8 + tq * 2;
                    float h0 = fmaxf(C[mt][nt][pair * 2 + 0] + bias_s[cl], 0.f);
                    float h1 = fmaxf(C[mt][nt][pair * 2 + 1] + bias_s[cl + 1], 0.f);
                    p0 += h0 * w2t_s[cl * 3 + 0] + h1 * w2t_s[(cl + 1) * 3 + 0];
                    p1 += h0 * w2t_s[cl * 3 + 1] + h1 * w2t_s[(cl + 1) * 3 + 1];
                    p2 += h0 * w2t_s[cl * 3 + 2] + h1 * w2t_s[(cl + 1) * 3 + 2];
                }
                p0 += __shfl_down_sync(0xffffffffu, p0, 2);
                p0 += __shfl_down_sync(0xffffffffu, p0, 1);
                p1 += __shfl_down_sync(0xffffffffu, p1, 2);
                p1 += __shfl_down_sync(0xffffffffu, p1, 1);
                p2 += __shfl_down_sync(0xffffffffu, p2, 2);
                p2 += __shfl_down_sync(0xffffffffu, p2, 1);
                if (tq == 0) {
                    int rl = wm * 64 + mt * 16 + pair * 8 + gr;
                    sred[rl * 12 + wn * 3 + 0] = p0;
                    sred[rl * 12 + wn * 3 + 1] = p1;
                    sred[rl * 12 + wn * 3 + 2] = p2;
                }
            }
        }
        __syncthreads();
        if (tid < 128) {
#pragma unroll
            for (int t = 0; t < 3; t++) {
                float s = sred[tid * 12 + t] + sred[tid * 12 + 3 + t] +
                          sred[tid * 12 + 6 + t] + sred[tid * 12 + 9 + t];
                atomicAdd(&g_s[(size_t)(rb + tid) * 18 + e * 3 + t], s);
            }
        }
    } else {
        float* bias_s = smf;
        if (tid < 128) bias_s[tid] = bp[cb + tid];
        __syncthreads();
#pragma unroll
        for (int mt = 0; mt < 4; mt++) {
#pragma unroll
            for (int nt = 0; nt < 4; nt++) {
                int row = rb + wm * 64 + mt * 16 + gr;
                int cl = wn * 32 + nt * 8 + tq * 2;
                float v0 = C[mt][nt][0] + bias_s[cl];
                float v1 = C[mt][nt][1] + bias_s[cl + 1];
                float v2 = C[mt][nt][2] + bias_s[cl];
                float v3 = C[mt][nt][3] + bias_s[cl + 1];
                if (MODE == 1) {
                    v0 = fmaxf(v0, 0.f); v1 = fmaxf(v1, 0.f);
                    v2 = fmaxf(v2, 0.f); v3 = fmaxf(v3, 0.f);
                    __half2 h0 = __halves2half2(__float2half_rn(v0), __float2half_rn(v1));
                    __half2 h1 = __halves2half2(__float2half_rn(v2), __float2half_rn(v3));
                    *(__half2*)(g_x1h + (size_t)row * HD + cb + cl) = h0;
                    *(__half2*)(g_x1h + (size_t)(row + 8) * HD + cb + cl) = h1;
                } else {
                    *(float2*)(g_x + (size_t)row * HD + cb + cl) = make_float2(v0, v1);
                    *(float2*)(g_x + (size_t)(row + 8) * HD + cb + cl) = make_float2(v2, v3);
                    __half2 h0 = __halves2half2(__float2half_rn(v0), __float2half_rn(v1));
                    __half2 h1 = __halves2half2(__float2half_rn(v2), __float2half_rn(v3));
                    *(__half2*)(g_xh + (size_t)row * HD + cb + cl) = h0;
                    *(__half2*)(g_xh + (size_t)(row + 8) * HD + cb + cl) = h1;
                }
            }
        }
    }
}

// ======================= small kernels =======================
__global__ void conv_h_k(const float* __restrict__ in, __half* __restrict__ out) {
    int idx = blockIdx.x * 256 + threadIdx.x;
    float4 v = ((const float4*)in)[idx];
    __half2 h0 = __halves2half2(__float2half_rn(v.x), __float2half_rn(v.y));
    __half2 h1 = __halves2half2(__float2half_rn(v.z), __float2half_rn(v.w));
    ((__half2*)out)[idx * 2 + 0] = h0;
    ((__half2*)out)[idx * 2 + 1] = h1;
}

__global__ void transpose_h_k(const float* __restrict__ W, __half* __restrict__ WT) {
    __shared__ float t[32][33];
    const float* Ws = W + (size_t)blockIdx.z * HD * HD;
    __half* Ts = WT + (size_t)blockIdx.z * HD * HD;
    int bx = blockIdx.x * 32, by = blockIdx.y * 32;
#pragma unroll
    for (int j = 0; j < 4; j++)
        t[threadIdx.y + 8 * j][threadIdx.x] =
            Ws[(size_t)(by + threadIdx.y + 8 * j) * HD + bx + threadIdx.x];
    __syncthreads();
#pragma unroll
    for (int j = 0; j < 4; j++)
        Ts[(size_t)(bx + threadIdx.y + 8 * j) * HD + by + threadIdx.x] =
            __float2half_rn(t[threadIdx.x][threadIdx.y + 8 * j]);
}

__global__ void zero_kernel() {
    int idx = blockIdx.x * 256 + threadIdx.x;
    if (idx < NT * EE * TT) g_s[idx] = 0.f;
    if (idx < TT * EE) { g_imp[idx] = 0.f; g_load[idx] = 0.f; }
    if (idx == 0) g_bce[0] = 0.f;
}

__global__ __launch_bounds__(256) void w2t_kernel(const float* __restrict__ w2,
                                                  const float* __restrict__ tw) {
    int g = blockIdx.x * 256 + threadIdx.x;
    int gw = g >> 5, lane = g & 31;
    if (gw >= EE * HD) return;
    const float* row = w2 + (size_t)gw * HD;
#pragma unroll
    for (int t = 0; t < TT; t++) {
        float a = 0.f;
        for (int o = lane; o < HD; o += 32) a += row[o] * tw[t * HD + o];
#pragma unroll
        for (int off = 16; off; off >>= 1) a += __shfl_down_sync(0xffffffffu, a, off);
        if (lane == 0) g_w2t[(size_t)gw * TT + t] = a;
    }
}

__global__ void b2dot_kernel(const float* __restrict__ b2, const float* __restrict__ tw) {
    int i = threadIdx.x;
    if (i < EE * TT) {
        int e = i / TT, t = i - TT * e;
        float a = 0.f;
        for (int o = 0; o < HD; o++) a += b2[e * HD + o] * tw[t * HD + o];
        g_b2dot[i] = a;
    }
}

__global__ __launch_bounds__(256) void gates_kernel(const float* __restrict__ wg) {
    int warp = threadIdx.x >> 5, lane = threadIdx.x & 31;
    int n = blockIdx.x * 8 + warp;
    const float* xr = g_x + (size_t)n * HD;
    float xv[32];
#pragma unroll
    for (int i = 0; i < 32; i++) xv[i] = xr[i * 32 + lane];
    float lg[18];
    for (int te = 0; te < 18; te++) {
        int t = te / 6, e = te - 6 * t;
        float acc = 0.f;
#pragma unroll
        for (int i = 0; i < 32; i++)
            acc += xv[i] * wg[((size_t)t * HD + i * 32 + lane) * EE + e];
#pragma unroll
        for (int off = 16; off; off >>= 1) acc += __shfl_down_sync(0xffffffffu, acc, off);
        lg[te] = acc;
    }
    if (lane == 0) {
        for (int t = 0; t < TT; t++) {
            float v[6];
#pragma unroll
            for (int e = 0; e < 6; e++) v[e] = lg[t * 6 + e];
            bool sel[6] = {false, false, false, false, false, false};
            float m = -1e30f;
            for (int r = 0; r < 3; r++) {  // strict >: first index wins (jax top_k)
                int bi = 0; float bv = -1e30f;
                for (int e = 0; e < 6; e++)
                    if (!sel[e] && v[e] > bv) { bv = v[e]; bi = e; }
                sel[bi] = true;
                if (r == 0) m = bv;
            }
            float sum = 0.f, gv[6];
            for (int e = 0; e < 6; e++) { gv[e] = sel[e] ? expf(v[e] - m) : 0.f; sum += gv[e]; }
            float inv = 1.f / sum;
            for (int e = 0; e < 6; e++) {
                float gg = gv[e] * inv;
                g_gates[(size_t)n * 18 + t * 6 + e] = gg;
                if (sel[e]) {
                    atomicAdd(&g_imp[t * 6 + e], gg);
                    atomicAdd(&g_load[t * 6 + e], 1.f);
                }
            }
        }
    }
}

__global__ void final_kernel(const float* __restrict__ scores,
                             const float* __restrict__ tower_b, float* __restrict__ out) {
    int b = blockIdx.x, c = threadIdx.x;
    int n = b * 64 + c;
    float sc[3];
#pragma unroll
    for (int t = 0; t < 3; t++) sc[t] = scores[(size_t)n * 3 + t];
    __shared__ float red[64];
    float mx[3];
    for (int t = 0; t < 3; t++) {
        red[c] = sc[t];
        __syncthreads();
        for (int off = 32; off; off >>= 1) {
            if (c < off) red[c] = fmaxf(red[c], red[c + off]);
            __syncthreads();
        }
        mx[t] = red[0];
        __syncthreads();
    }
    float zsum = 0.f, bsum = 0.f;
#pragma unroll
    for (int t = 0; t < 3; t++) {
        float z = tower_b[t];
#pragma unroll
        for (int e = 0; e < 6; e++)
            z += g_gates[(size_t)n * 18 + t * 6 + e] *
                 (g_s[(size_t)n * 18 + e * 3 + t] + g_b2dot[e * 3 + t]);
        float label = (sc[t] == mx[t]) ? 1.f : 0.f;
        bsum += fmaxf(z, 0.f) - z * label + log1pf(expf(-fabsf(z)));
        zsum += z;
    }
    out[1 + n] = 1.f / (1.f + expf(-zsum / 3.f));
    red[c] = bsum;
    __syncthreads();
    for (int off = 32; off; off >>= 1) {
        if (c < off) red[c] += red[c + off];
        __syncthreads();
    }
    if (c == 0) atomicAdd(&g_bce[0], red[0]);
}

__global__ void finalize_kernel(float* __restrict__ out) {
    if (threadIdx.x == 0 && blockIdx.x == 0) {
        float aux = 0.f;
        for (int t = 0; t < 3; t++) {
            for (int which = 0; which < 2; which++) {
                const float* v = which ? &g_load[t * 6] : &g_imp[t * 6];
                float m = 0.f;
                for (int e = 0; e < 6; e++) m += v[e];
                m *= (1.f / 6.f);
                float var = 0.f;
                for (int e = 0; e < 6; e++) { float d = v[e] - m; var += d * d; }
                var *= (1.f / 5.f);  // ddof=1
                aux += var / (m * m + 1e-10f);
            }
        }
        out[0] = g_bce[0] / 24576.f + 0.01f * aux;
    }
}

// ======================= launch =======================
extern "C" void kernel_launch(void* const* d_in, const int* in_sizes, int n_in,
                              void* d_out, int out_size) {
    const float* encs   = (const float*)d_in[0];
    const float* scores = (const float*)d_in[1];
    const float* fc1_w  = (const float*)d_in[2];
    const float* fc1_b  = (const float*)d_in[3];
    const float* fc2_w  = (const float*)d_in[4];
    const float* fc2_b  = (const float*)d_in[5];
    const float* w_gate = (const float*)d_in[6];
    const float* ew1    = (const float*)d_in[7];
    const float* eb1    = (const float*)d_in[8];
    const float* ew2    = (const float*)d_in[9];
    const float* eb2    = (const float*)d_in[10];
    const float* tw     = (const float*)d_in[11];
    const float* tb     = (const float*)d_in[12];
    float* out = (float*)d_out;

    cudaFuncSetAttribute(gemm_mma<0>, cudaFuncAttributeMaxDynamicSharedMemorySize, GSMEM);
    cudaFuncSetAttribute(gemm_mma<1>, cudaFuncAttributeMaxDynamicSharedMemorySize, GSMEM);
    cudaFuncSetAttribute(gemm_mma<2>, cudaFuncAttributeMaxDynamicSharedMemorySize, GSMEM);

    __half *ench, *wt1h, *wt2h, *wteh;
    cudaGetSymbolAddress((void**)&ench, g_ench);
    cudaGetSymbolAddress((void**)&wt1h, g_wt1h);
    cudaGetSymbolAddress((void**)&wt2h, g_wt2h);
    cudaGetSymbolAddress((void**)&wteh, g_wteh);

    zero_kernel<<<(NT * EE * TT + 255) / 256, 256>>>();
    conv_h_k<<<NT * HD / 4 / 256, 256>>>(encs, ench);
    transpose_h_k<<<dim3(32, 32, 1), dim3(32, 8)>>>(fc1_w, wt1h);
    transpose_h_k<<<dim3(32, 32, 1), dim3(32, 8)>>>(fc2_w, wt2h);
    transpose_h_k<<<dim3(32, 32, EE), dim3(32, 8)>>>(ew1, wteh);
    w2t_kernel<<<(EE * HD * 32 + 255) / 256, 256>>>(ew2, tw);
    b2dot_kernel<<<1, 32>>>(eb2, tw);

    dim3 gfc(HD / BN, NT / BM, 1);
    gemm_mma<1><<<gfc, 256, GSMEM>>>(fc1_b);   // x1 = relu(encs@fc1+b)  -> fp16
    gemm_mma<0><<<gfc, 256, GSMEM>>>(fc2_b);   // x  = x1@fc2+b          -> fp32 + fp16

    gates_kernel<<<NT / 8, 256>>>(w_gate);

    dim3 ge(HD / BN, NT / BM, EE);
    gemm_mma<2><<<ge, 256, GSMEM>>>(eb1);      // fused expert up-proj + s

    final_kernel<<<128, 64>>>(scores, tb, out);
    finalize_kernel<<<1, 32>>>(out);
}

// round 7
// speedup vs baseline: 5.5786x; 1.0811x over previous
#include <cuda_runtime.h>
#include <cuda_fp16.h>
#include <math.h>
#include <cstdint>

#define NT 8192   // B*C tokens
#define HD 1024
#define TT 3
#define EE 6

// ---- scratch (device globals; no allocation allowed) ----
__device__ __half g_ench[NT * HD];       // fp16 encs
__device__ __half g_x1h[NT * HD];        // fp16 relu(fc1)
__device__ float  g_x[NT * HD];          // fp32 shared-bottom out (for gates)
__device__ __half g_xh[NT * HD];         // fp16 copy (expert GEMM A)
__device__ __half g_wt1h[HD * HD];       // fc1_w^T fp16
__device__ __half g_wt2h[HD * HD];       // fc2_w^T fp16
__device__ __half g_wteh[EE * HD * HD];  // expert_w1^T fp16
__device__ float g_gates[NT * TT * EE];
__device__ float g_s[NT * EE * TT];
__device__ float g_w2t[EE * HD * TT];
__device__ float g_b2dot[EE * TT];
__device__ float g_imp[TT * EE];
__device__ float g_load[TT * EE];
__device__ float g_bce[1];

// ======================= helpers =======================
__device__ __forceinline__ uint32_t smem_u32(const void* p) {
    uint32_t a;
    asm("{ .reg .u64 t; cvta.to.shared.u64 t, %1; cvt.u32.u64 %0, t; }" : "=r"(a) : "l"(p));
    return a;
}
__device__ __forceinline__ void cpa16(uint32_t dst, const void* src) {
    asm volatile("cp.async.cg.shared.global [%0], [%1], 16;" :: "r"(dst), "l"(src));
}
#define CPA_COMMIT() asm volatile("cp.async.commit_group;" ::: "memory")
#define CPA_WAIT(n)  asm volatile("cp.async.wait_group %0;" :: "n"(n) : "memory")

__device__ __forceinline__ void mma16(float* c, const uint32_t* a, const uint32_t* b) {
    asm volatile(
        "mma.sync.aligned.m16n8k16.row.col.f32.f16.f16.f32 "
        "{%0,%1,%2,%3}, {%4,%5,%6,%7}, {%8,%9}, {%0,%1,%2,%3};"
        : "+f"(c[0]), "+f"(c[1]), "+f"(c[2]), "+f"(c[3])
        : "r"(a[0]), "r"(a[1]), "r"(a[2]), "r"(a[3]), "r"(b[0]), "r"(b[1]));
}
__device__ __forceinline__ void ldsm4(uint32_t* r, uint32_t addr) {
    asm volatile("ldmatrix.sync.aligned.m8n8.x4.shared.b16 {%0,%1,%2,%3}, [%4];"
                 : "=r"(r[0]), "=r"(r[1]), "=r"(r[2]), "=r"(r[3]) : "r"(addr));
}

// ======================= fp16 mma.sync GEMM =======================
// C[8192,1024] = A[8192,1024] @ W[1024,1024]; B operand = W^T (row n, k contiguous).
constexpr int BM = 128, BN = 128;
constexpr int BKH = 32;                  // k-halves per slab
constexpr int BKP = 40;                  // padded row length in halves (80 B)
constexpr int NS = HD / BKH;             // 32 slabs
constexpr int STG_B = (BM + BN) * BKP * 2;  // 20480 bytes per stage
constexpr int GSMEM = 3 * STG_B;            // 61440 B

// MODE 0: fc2 (A=g_x1h -> g_x fp32 + g_xh fp16)  MODE 1: fc1 (A=g_ench -> g_x1h, relu)
// MODE 2: expert (A=g_xh, bias+relu, fused s-epilogue)
template <int MODE>
__global__ __launch_bounds__(256, 2) void gemm_mma(const float* __restrict__ bias_in) {
    extern __shared__ __align__(16) char smb[];
    const uint32_t sb = smem_u32(smb);
    float* smf = (float*)smb;
    const int tid = threadIdx.x;
    const int wid = tid >> 5, lane = tid & 31;
    const int wm = wid >> 2, wn = wid & 3;     // warp grid 2(M) x 4(N)
    const int gr = lane >> 2, tq = lane & 3;   // quad row / quad col
    const int e = blockIdx.z;
    const int rb = blockIdx.y * BM, cb = blockIdx.x * BN;

    const __half* A = (MODE == 1) ? g_ench : (MODE == 0 ? g_x1h : g_xh);
    const __half* Bw = (MODE == 1) ? g_wt1h
                                   : (MODE == 0 ? g_wt2h : g_wteh + (size_t)e * HD * HD);
    const float* bp = bias_in + (MODE == 2 ? (size_t)e * HD : 0);

    float C[4][4][4];
#pragma unroll
    for (int i = 0; i < 4; i++)
#pragma unroll
        for (int j = 0; j < 4; j++)
#pragma unroll
            for (int q = 0; q < 4; q++) C[i][j][q] = 0.f;

    // ---- precomputed ldmatrix lane offsets (in halves, relative to tile bases) ----
    // A 16x16 tile: row = lane&15, k-block = (lane>>4)*8
    const uint32_t a_lane_off = (uint32_t)((lane & 15) * BKP + (lane >> 4) * 8) * 2;
    // B 16(n)x16(k) tile: n-row = (lane>>4)*8 + (lane&7), k-block = ((lane>>3)&1)*8
    const uint32_t b_lane_off =
        (uint32_t)(((lane >> 4) * 8 + (lane & 7)) * BKP + ((lane >> 3) & 1) * 8) * 2;

    // ---- slab loader: slab p -> stage s (rows of 32 halves = 4x16B segs) ----
    auto load_slab = [&](int p, int s) {
        const int k0 = p * BKH;
        const uint32_t As_a = sb + (uint32_t)(s * STG_B);
        const uint32_t Bs_a = As_a + (uint32_t)(BM * BKP * 2);
#pragma unroll
        for (int j = 0; j < 2; j++) {
            int c = tid + j * 256;               // 0..511
            int row = c >> 2, seg = c & 3;
            uint32_t off = (uint32_t)(row * BKP * 2 + seg * 16);
            cpa16(As_a + off, A + (size_t)(rb + row) * HD + k0 + seg * 8);
            cpa16(Bs_a + off, Bw + (size_t)(cb + row) * HD + k0 + seg * 8);
        }
        CPA_COMMIT();
    };

    load_slab(0, 0);
    load_slab(1, 1);

    for (int i = 0; i < NS; i++) {
        if (i + 1 < NS) { CPA_WAIT(1); } else { CPA_WAIT(0); }
        __syncthreads();
        if (i + 2 < NS) load_slab(i + 2, (i + 2) % 3);

        const uint32_t As_u = sb + (uint32_t)((i % 3) * STG_B);
        const uint32_t Bs_u = As_u + (uint32_t)(BM * BKP * 2);
        const uint32_t a_base = As_u + (uint32_t)(wm * 64 * BKP) * 2 + a_lane_off;
        const uint32_t b_base = Bs_u + (uint32_t)(wn * 32 * BKP) * 2 + b_lane_off;
#pragma unroll
        for (int ks = 0; ks < 2; ks++) {
            const uint32_t kb = (uint32_t)(ks * 16) * 2;  // bytes
            uint32_t a[4][4], b[2][4];
#pragma unroll
            for (int mt = 0; mt < 4; mt++)
                ldsm4(a[mt], a_base + (uint32_t)(mt * 16 * BKP) * 2 + kb);
#pragma unroll
            for (int np = 0; np < 2; np++)
                ldsm4(b[np], b_base + (uint32_t)(np * 16 * BKP) * 2 + kb);
#pragma unroll
            for (int mt = 0; mt < 4; mt++) {
#pragma unroll
                for (int np = 0; np < 2; np++) {
                    mma16(C[mt][2 * np + 0], a[mt], &b[np][0]);
                    mma16(C[mt][2 * np + 1], a[mt], &b[np][2]);
                }
            }
        }
        __syncthreads();
    }

    // ---- epilogue ----
    if (MODE == 2) {
        float* w2t_s = smf;            // 384
        float* bias_s = smf + 384;     // 128
        float* sred = smf + 512;       // 128*12
        if (tid < 128) bias_s[tid] = bp[cb + tid];
        for (int idx = tid; idx < 384; idx += 256)
            w2t_s[idx] = g_w2t[(size_t)e * HD * 3 + (size_t)cb * 3 + idx];
        __syncthreads();
#pragma unroll
        for (int mt = 0; mt < 4; mt++) {
#pragma unroll
            for (int pair = 0; pair < 2; pair++) {
                float p0 = 0.f, p1 = 0.f, p2 = 0.f;
#pragma unroll
                for (int nt = 0; nt < 4; nt++) {
                    int cl = wn * 32 + nt * 8 + tq * 2;
                    float h0 = fmaxf(C[mt][nt][pair * 2 + 0] + bias_s[cl], 0.f);
                    float h1 = fmaxf(C[mt][nt][pair * 2 + 1] + bias_s[cl + 1], 0.f);
                    p0 += h0 * w2t_s[cl * 3 + 0] + h1 * w2t_s[(cl + 1) * 3 + 0];
                    p1 += h0 * w2t_s[cl * 3 + 1] + h1 * w2t_s[(cl + 1) * 3 + 1];
                    p2 += h0 * w2t_s[cl * 3 + 2] + h1 * w2t_s[(cl + 1) * 3 + 2];
                }
                p0 += __shfl_down_sync(0xffffffffu, p0, 2);
                p0 += __shfl_down_sync(0xffffffffu, p0, 1);
                p1 += __shfl_down_sync(0xffffffffu, p1, 2);
                p1 += __shfl_down_sync(0xffffffffu, p1, 1);
                p2 += __shfl_down_sync(0xffffffffu, p2, 2);
                p2 += __shfl_down_sync(0xffffffffu, p2, 1);
                if (tq == 0) {
                    int rl = wm * 64 + mt * 16 + pair * 8 + gr;
                    sred[rl * 12 + wn * 3 + 0] = p0;
                    sred[rl * 12 + wn * 3 + 1] = p1;
                    sred[rl * 12 + wn * 3 + 2] = p2;
                }
            }
        }
        __syncthreads();
        if (tid < 128) {
#pragma unroll
            for (int t = 0; t < 3; t++) {
                float s = sred[tid * 12 + t] + sred[tid * 12 + 3 + t] +
                          sred[tid * 12 + 6 + t] + sred[tid * 12 + 9 + t];
                atomicAdd(&g_s[(size_t)(rb + tid) * 18 + e * 3 + t], s);
            }
        }
    } else {
        float* bias_s = smf;
        if (tid < 128) bias_s[tid] = bp[cb + tid];
        __syncthreads();
#pragma unroll
        for (int mt = 0; mt < 4; mt++) {
#pragma unroll
            for (int nt = 0; nt < 4; nt++) {
                int row = rb + wm * 64 + mt * 16 + gr;
                int cl = wn * 32 + nt * 8 + tq * 2;
                float v0 = C[mt][nt][0] + bias_s[cl];
                float v1 = C[mt][nt][1] + bias_s[cl + 1];
                float v2 = C[mt][nt][2] + bias_s[cl];
                float v3 = C[mt][nt][3] + bias_s[cl + 1];
                if (MODE == 1) {
                    v0 = fmaxf(v0, 0.f); v1 = fmaxf(v1, 0.f);
                    v2 = fmaxf(v2, 0.f); v3 = fmaxf(v3, 0.f);
                    __half2 h0 = __halves2half2(__float2half_rn(v0), __float2half_rn(v1));
                    __half2 h1 = __halves2half2(__float2half_rn(v2), __float2half_rn(v3));
                    *(__half2*)(g_x1h + (size_t)row * HD + cb + cl) = h0;
                    *(__half2*)(g_x1h + (size_t)(row + 8) * HD + cb + cl) = h1;
                } else {
                    *(float2*)(g_x + (size_t)row * HD + cb + cl) = make_float2(v0, v1);
                    *(float2*)(g_x + (size_t)(row + 8) * HD + cb + cl) = make_float2(v2, v3);
                    __half2 h0 = __halves2half2(__float2half_rn(v0), __float2half_rn(v1));
                    __half2 h1 = __halves2half2(__float2half_rn(v2), __float2half_rn(v3));
                    *(__half2*)(g_xh + (size_t)row * HD + cb + cl) = h0;
                    *(__half2*)(g_xh + (size_t)(row + 8) * HD + cb + cl) = h1;
                }
            }
        }
    }
}

// ======================= small kernels =======================
__global__ void conv_h_k(const float* __restrict__ in, __half* __restrict__ out) {
    int idx = blockIdx.x * 256 + threadIdx.x;
    float4 v = ((const float4*)in)[idx];
    __half2 h0 = __halves2half2(__float2half_rn(v.x), __float2half_rn(v.y));
    __half2 h1 = __halves2half2(__float2half_rn(v.z), __float2half_rn(v.w));
    ((__half2*)out)[idx * 2 + 0] = h0;
    ((__half2*)out)[idx * 2 + 1] = h1;
}

__global__ void transpose_h_k(const float* __restrict__ W, __half* __restrict__ WT) {
    __shared__ float t[32][33];
    const float* Ws = W + (size_t)blockIdx.z * HD * HD;
    __half* Ts = WT + (size_t)blockIdx.z * HD * HD;
    int bx = blockIdx.x * 32, by = blockIdx.y * 32;
#pragma unroll
    for (int j = 0; j < 4; j++)
        t[threadIdx.y + 8 * j][threadIdx.x] =
            Ws[(size_t)(by + threadIdx.y + 8 * j) * HD + bx + threadIdx.x];
    __syncthreads();
#pragma unroll
    for (int j = 0; j < 4; j++)
        Ts[(size_t)(bx + threadIdx.y + 8 * j) * HD + by + threadIdx.x] =
            __float2half_rn(t[threadIdx.x][threadIdx.y + 8 * j]);
}

__global__ void zero_kernel() {
    int idx = blockIdx.x * 256 + threadIdx.x;
    if (idx < NT * EE * TT) g_s[idx] = 0.f;
    if (idx < TT * EE) { g_imp[idx] = 0.f; g_load[idx] = 0.f; }
    if (idx == 0) g_bce[0] = 0.f;
}

__global__ __launch_bounds__(256) void w2t_kernel(const float* __restrict__ w2,
                                                  const float* __restrict__ tw) {
    int g = blockIdx.x * 256 + threadIdx.x;
    int gw = g >> 5, lane = g & 31;
    if (gw >= EE * HD) return;
    const float* row = w2 + (size_t)gw * HD;
#pragma unroll
    for (int t = 0; t < TT; t++) {
        float a = 0.f;
        for (int o = lane; o < HD; o += 32) a += row[o] * tw[t * HD + o];
#pragma unroll
        for (int off = 16; off; off >>= 1) a += __shfl_down_sync(0xffffffffu, a, off);
        if (lane == 0) g_w2t[(size_t)gw * TT + t] = a;
    }
}

__global__ void b2dot_kernel(const float* __restrict__ b2, const float* __restrict__ tw) {
    int i = threadIdx.x;
    if (i < EE * TT) {
        int e = i / TT, t = i - TT * e;
        float a = 0.f;
        for (int o = 0; o < HD; o++) a += b2[e * HD + o] * tw[t * HD + o];
        g_b2dot[i] = a;
    }
}

__global__ __launch_bounds__(256) void gates_kernel(const float* __restrict__ wg) {
    int warp = threadIdx.x >> 5, lane = threadIdx.x & 31;
    int n = blockIdx.x * 8 + warp;
    const float* xr = g_x + (size_t)n * HD;
    float xv[32];
#pragma unroll
    for (int i = 0; i < 32; i++) xv[i] = xr[i * 32 + lane];
    float lg[18];
    for (int te = 0; te < 18; te++) {
        int t = te / 6, e = te - 6 * t;
        float acc = 0.f;
#pragma unroll
        for (int i = 0; i < 32; i++)
            acc += xv[i] * wg[((size_t)t * HD + i * 32 + lane) * EE + e];
#pragma unroll
        for (int off = 16; off; off >>= 1) acc += __shfl_down_sync(0xffffffffu, acc, off);
        lg[te] = acc;
    }
    if (lane == 0) {
        for (int t = 0; t < TT; t++) {
            float v[6];
#pragma unroll
            for (int e = 0; e < 6; e++) v[e] = lg[t * 6 + e];
            bool sel[6] = {false, false, false, false, false, false};
            float m = -1e30f;
            for (int r = 0; r < 3; r++) {  // strict >: first index wins (jax top_k)
                int bi = 0; float bv = -1e30f;
                for (int e = 0; e < 6; e++)
                    if (!sel[e] && v[e] > bv) { bv = v[e]; bi = e; }
                sel[bi] = true;
                if (r == 0) m = bv;
            }
            float sum = 0.f, gv[6];
            for (int e = 0; e < 6; e++) { gv[e] = sel[e] ? expf(v[e] - m) : 0.f; sum += gv[e]; }
            float inv = 1.f / sum;
            for (int e = 0; e < 6; e++) {
                float gg = gv[e] * inv;
                g_gates[(size_t)n * 18 + t * 6 + e] = gg;
                if (sel[e]) {
                    atomicAdd(&g_imp[t * 6 + e], gg);
                    atomicAdd(&g_load[t * 6 + e], 1.f);
                }
            }
        }
    }
}

__global__ void final_kernel(const float* __restrict__ scores,
                             const float* __restrict__ tower_b, float* __restrict__ out) {
    int b = blockIdx.x, c = threadIdx.x;
    int n = b * 64 + c;
    float sc[3];
#pragma unroll
    for (int t = 0; t < 3; t++) sc[t] = scores[(size_t)n * 3 + t];
    __shared__ float red[64];
    float mx[3];
    for (int t = 0; t < 3; t++) {
        red[c] = sc[t];
        __syncthreads();
        for (int off = 32; off; off >>= 1) {
            if (c < off) red[c] = fmaxf(red[c], red[c + off]);
            __syncthreads();
        }
        mx[t] = red[0];
        __syncthreads();
    }
    float zsum = 0.f, bsum = 0.f;
#pragma unroll
    for (int t = 0; t < 3; t++) {
        float z = tower_b[t];
#pragma unroll
        for (int e = 0; e < 6; e++)
            z += g_gates[(size_t)n * 18 + t * 6 + e] *
                 (g_s[(size_t)n * 18 + e * 3 + t] + g_b2dot[e * 3 + t]);
        float label = (sc[t] == mx[t]) ? 1.f : 0.f;
        bsum += fmaxf(z, 0.f) - z * label + log1pf(expf(-fabsf(z)));
        zsum += z;
    }
    out[1 + n] = 1.f / (1.f + expf(-zsum / 3.f));
    red[c] = bsum;
    __syncthreads();
    for (int off = 32; off; off >>= 1) {
        if (c < off) red[c] += red[c + off];
        __syncthreads();
    }
    if (c == 0) atomicAdd(&g_bce[0], red[0]);
}

__global__ void finalize_kernel(float* __restrict__ out) {
    if (threadIdx.x == 0 && blockIdx.x == 0) {
        float aux = 0.f;
        for (int t = 0; t < 3; t++) {
            for (int which = 0; which < 2; which++) {
                const float* v = which ? &g_load[t * 6] : &g_imp[t * 6];
                float m = 0.f;
                for (int e = 0; e < 6; e++) m += v[e];
                m *= (1.f / 6.f);
                float var = 0.f;
                for (int e = 0; e < 6; e++) { float d = v[e] - m; var += d * d; }
                var *= (1.f / 5.f);  // ddof=1
                aux += var / (m * m + 1e-10f);
            }
        }
        out[0] = g_bce[0] / 24576.f + 0.01f * aux;
    }
}

// ======================= launch =======================
extern "C" void kernel_launch(void* const* d_in, const int* in_sizes, int n_in,
                              void* d_out, int out_size) {
    const float* encs   = (const float*)d_in[0];
    const float* scores = (const float*)d_in[1];
    const float* fc1_w  = (const float*)d_in[2];
    const float* fc1_b  = (const float*)d_in[3];
    const float* fc2_w  = (const float*)d_in[4];
    const float* fc2_b  = (const float*)d_in[5];
    const float* w_gate = (const float*)d_in[6];
    const float* ew1    = (const float*)d_in[7];
    const float* eb1    = (const float*)d_in[8];
    const float* ew2    = (const float*)d_in[9];
    const float* eb2    = (const float*)d_in[10];
    const float* tw     = (const float*)d_in[11];
    const float* tb     = (const float*)d_in[12];
    float* out = (float*)d_out;

    cudaFuncSetAttribute(gemm_mma<0>, cudaFuncAttributeMaxDynamicSharedMemorySize, GSMEM);
    cudaFuncSetAttribute(gemm_mma<1>, cudaFuncAttributeMaxDynamicSharedMemorySize, GSMEM);
    cudaFuncSetAttribute(gemm_mma<2>, cudaFuncAttributeMaxDynamicSharedMemorySize, GSMEM);

    __half *ench, *wt1h, *wt2h, *wteh;
    cudaGetSymbolAddress((void**)&ench, g_ench);
    cudaGetSymbolAddress((void**)&wt1h, g_wt1h);
    cudaGetSymbolAddress((void**)&wt2h, g_wt2h);
    cudaGetSymbolAddress((void**)&wteh, g_wteh);

    zero_kernel<<<(NT * EE * TT + 255) / 256, 256>>>();
    conv_h_k<<<NT * HD / 4 / 256, 256>>>(encs, ench);
    transpose_h_k<<<dim3(32, 32, 1), dim3(32, 8)>>>(fc1_w, wt1h);
    transpose_h_k<<<dim3(32, 32, 1), dim3(32, 8)>>>(fc2_w, wt2h);
    transpose_h_k<<<dim3(32, 32, EE), dim3(32, 8)>>>(ew1, wteh);
    w2t_kernel<<<(EE * HD * 32 + 255) / 256, 256>>>(ew2, tw);
    b2dot_kernel<<<1, 32>>>(eb2, tw);

    dim3 gfc(HD / BN, NT / BM, 1);
    gemm_mma<1><<<gfc, 256, GSMEM>>>(fc1_b);   // x1 = relu(encs@fc1+b)  -> fp16
    gemm_mma<0><<<gfc, 256, GSMEM>>>(fc2_b);   // x  = x1@fc2+b          -> fp32 + fp16

    gates_kernel<<<NT / 8, 256>>>(w_gate);

    dim3 ge(HD / BN, NT / BM, EE);
    gemm_mma<2><<<ge, 256, GSMEM>>>(eb1);      // fused expert up-proj + s

    final_kernel<<<128, 64>>>(scores, tb, out);
    finalize_kernel<<<1, 32>>>(out);
}